// round 11
// baseline (speedup 1.0000x reference)
#include <cuda_runtime.h>

// CapsuleLayer dynamic routing: 3 streaming passes (u_hat recomputed from W;
// b_ij == u_hat·(v0+..+v_{r-1})) + 3 squash kernels.
// R10: pass 0 rewritten with lane=b (all W shared reads lane-uniform ->
// broadcast crossbar, 16 warps, no softmax so no per-i barrier). Passes 1/2
// keep the R9 structure with vectorized x loads. Squash gets 6-way MLP.

#define BB 32
#define JJ 32
#define II 4608
#define DA 8
#define DD 16
#define CHUNK 32
#define NCHUNK 144
#define OUTSZ (BB * JJ * DD)   // 16384
#define CAP_EPS 1e-7f
#define VSTRIDE 20             // padded v row: conflict-free LDS.128

typedef unsigned long long u64;

__device__ float g_partial[NCHUNK * OUTSZ]; // per-chunk partial s (9.4 MB)
__device__ float g_vsum[OUTSZ];             // v0, then v0+v1

__device__ __forceinline__ u64 pack2(float x, float y) {
    u64 r; asm("mov.b64 %0, {%1, %2};" : "=l"(r) : "f"(x), "f"(y)); return r;
}
__device__ __forceinline__ void unpack2(u64 v, float& x, float& y) {
    asm("mov.b64 {%0, %1}, %2;" : "=f"(x), "=f"(y) : "l"(v));
}
__device__ __forceinline__ u64 ffma2(u64 a, u64 b, u64 c) {
    u64 d; asm("fma.rn.f32x2 %0, %1, %2, %3;" : "=l"(d) : "l"(a), "l"(b), "l"(c)); return d;
}

// ---- W tile store: transpose [d][a] -> [a][d] with float4-XOR swizzle ------
// Global float4 f (0..31) of row holds d = f>>1, a = 4*(f&1)+component.
// Target float z' = a*16+d at  phys = row + ((z'>>2) ^ sj)*4 + (z'&3).
__device__ __forceinline__ void stw(float* row, float4 v, int f, int sj) {
    const int base = 16 * (f & 1) + (f >> 3);
    const int lo   = (f >> 1) & 3;
    row[(((base + 0 ) ^ sj) << 2) + lo] = v.x;
    row[(((base + 4 ) ^ sj) << 2) + lo] = v.y;
    row[(((base + 8 ) ^ sj) << 2) + lo] = v.z;
    row[(((base + 12) ^ sj) << 2) + lo] = v.w;
}

// R9-style staging for 256-thread kernels (thread handles 4 float4 of a row)
__device__ __forceinline__ void stage_load(float4* g, const float4* Wg4,
                                           int sj, int sf, int ig) {
#pragma unroll
    for (int k = 0; k < 4; k++) g[k] = Wg4[(sj * II + ig) * 32 + k * 8 + sf];
}
__device__ __forceinline__ void stage_store(float* slot, const float4* g,
                                            int sj, int sq0, int ssub) {
    float* row = slot + sj * 128;
#pragma unroll
    for (int k = 0; k < 4; k++) {
        row[((sq0 + 0  + k) ^ sj) * 4 + ssub] = g[k].x;
        row[((sq0 + 4  + k) ^ sj) * 4 + ssub] = g[k].y;
        row[((sq0 + 8  + k) ^ sj) * 4 + ssub] = g[k].z;
        row[((sq0 + 12 + k) ^ sj) * 4 + ssub] = g[k].w;
    }
}

// ---------------------------------------------------------------------------
// PASS 0: uniform c (folded into squash). lane = b, 512 threads = 16 warps,
// warp w owns j = 2w, 2w+1. All W shared reads lane-uniform -> broadcast.
// Shared (98304 B): [0,16384) W ring 4 slots | [16384,24576) x transposed
//   XT[(il*8+a)*32 + b]
// ---------------------------------------------------------------------------
__global__ void __launch_bounds__(512, 1)
pass0_kernel(const float* __restrict__ xg, const float* __restrict__ Wg) {
    extern __shared__ float sh[];
    float* xsh = sh + 16384;
    const float4* Wg4 = (const float4*)Wg;
    const int t  = threadIdx.x;
    const int b  = t & 31;         // lane = batch
    const int w  = t >> 5;         // warp 0..15
    const int i0 = blockIdx.x * CHUNK;
    const int sj = t >> 4;         // staging row 0..31
    const int q  = t & 15;         // staging float4 sub-index

    // x transpose: xg[b, i0+il, a] -> XT[(il*8+a)*32 + b]
#pragma unroll
    for (int k = 0; k < 16; k++) {
        int e = t + k * 512;
        int bb = e >> 8, rem = e & 255;
        xsh[rem * 32 + bb] = xg[bb * (II * DA) + i0 * DA + rem];
    }

    // W prologue: tiles 0,1 staged; tile 2 prefetched
    float4 g0, g1;
    g0 = Wg4[(sj * II + i0 + 0) * 32 + q];
    g1 = Wg4[(sj * II + i0 + 0) * 32 + q + 16];
    stw(sh + sj * 128, g0, q, sj);
    stw(sh + sj * 128, g1, q + 16, sj);
    g0 = Wg4[(sj * II + i0 + 1) * 32 + q];
    g1 = Wg4[(sj * II + i0 + 1) * 32 + q + 16];
    stw(sh + 4096 + sj * 128, g0, q, sj);
    stw(sh + 4096 + sj * 128, g1, q + 16, sj);
    g0 = Wg4[(sj * II + i0 + 2) * 32 + q];
    g1 = Wg4[(sj * II + i0 + 2) * 32 + q + 16];
    __syncthreads();

    u64 acc2[2][DD / 2];
#pragma unroll
    for (int jj = 0; jj < 2; jj++)
#pragma unroll
        for (int dp = 0; dp < DD / 2; dp++) acc2[jj][dp] = 0ull;

    auto compute0 = [&](int il) {
        const ulonglong2* slot = (const ulonglong2*)(sh + ((il & 3) << 12));
        const float* xb = xsh + il * 8 * 32;
        u64 xx[DA];
#pragma unroll
        for (int a = 0; a < DA; a++) {
            float xv = xb[a * 32 + b];            // conflict-free per-lane
            xx[a] = pack2(xv, xv);
        }
#pragma unroll
        for (int jj = 0; jj < 2; jj++) {
            const int j = 2 * w + jj;
            const ulonglong2* wb = slot + j * 32; // row j (128 floats)
#pragma unroll
            for (int a = 0; a < DA; a++) {
#pragma unroll
                for (int d4 = 0; d4 < 4; d4++) {
                    ulonglong2 wv = wb[((a << 2) | d4) ^ j];  // broadcast
                    acc2[jj][2 * d4]     = ffma2(wv.x, xx[a], acc2[jj][2 * d4]);
                    acc2[jj][2 * d4 + 1] = ffma2(wv.y, xx[a], acc2[jj][2 * d4 + 1]);
                }
            }
        }
    };

    for (int pp = 0; pp < CHUNK / 2; ++pp) {
        const int il0 = 2 * pp;
        compute0(il0);
        if (pp + 1 < CHUNK / 2) {
            // slot (il0+2)&3 last read at il0-2 (before previous barrier)
            float* row = sh + (((il0 + 2) & 3) << 12) + sj * 128;
            stw(row, g0, q, sj);
            stw(row, g1, q + 16, sj);
            g0 = Wg4[(sj * II + i0 + il0 + 3) * 32 + q];
            g1 = Wg4[(sj * II + i0 + il0 + 3) * 32 + q + 16];
        }
        compute0(il0 + 1);
        if (pp + 1 < CHUNK / 2) {
            float* row = sh + (((il0 + 3) & 3) << 12) + sj * 128;
            stw(row, g0, q, sj);
            stw(row, g1, q + 16, sj);
            if (pp + 2 < CHUNK / 2) {
                g0 = Wg4[(sj * II + i0 + il0 + 4) * 32 + q];
                g1 = Wg4[(sj * II + i0 + il0 + 4) * 32 + q + 16];
            }
            __syncthreads();
        }
    }

#pragma unroll
    for (int jj = 0; jj < 2; jj++) {
        u64* p = (u64*)&g_partial[((blockIdx.x * BB + b) * JJ + (2 * w + jj)) * DD];
#pragma unroll
        for (int dp = 0; dp < DD / 2; dp++) p[dp] = acc2[jj][dp];
    }
}

// ---------------------------------------------------------------------------
// PASS 1/2 (R9 structure): 256 threads, lane=j, warp owns 4 batches.
// Shared (180224 B): ring | x chunk | padded v.
// ---------------------------------------------------------------------------
template <int PASS>
__global__ void __launch_bounds__(256, 1)
pass_kernel(const float* __restrict__ xg, const float* __restrict__ Wg) {
    extern __shared__ float sh[];
    float* xsh = sh + 16384;
    float* vsh = sh + 24576;
    const float4* Wg4 = (const float4*)Wg;

    const int t  = threadIdx.x;
    const int j  = t & 31;
    const int w  = t >> 5;
    const int b0 = w * 4;
    const int i0 = blockIdx.x * CHUNK;
    const int sj   = t >> 3;
    const int sf   = t & 7;
    const int ssub = sf >> 1;
    const int sq0  = (sf & 1) << 4;

    // v -> padded shared
    for (int e = t; e < OUTSZ; e += 256) {
        int bj = e >> 4;
        vsh[bj * VSTRIDE + (e & 15)] = g_vsum[e];
    }
    // x: full chunk, contiguous 256 floats per b
    for (int idx = t; idx < 8192; idx += 256) {
        int b = idx >> 8;
        xsh[idx] = xg[b * (II * DA) + i0 * DA + (idx & 255)];
    }

    float4 g[4];
    stage_load(g, Wg4, sj, sf, i0 + 0);
    stage_store(sh, g, sj, sq0, ssub);
    stage_load(g, Wg4, sj, sf, i0 + 1);
    stage_store(sh + 4096, g, sj, sq0, ssub);
    stage_load(g, Wg4, sj, sf, i0 + 2);
    __syncthreads();

    u64 acc2[4][DD / 2];
#pragma unroll
    for (int bi = 0; bi < 4; bi++)
#pragma unroll
        for (int dp = 0; dp < DD / 2; dp++) acc2[bi][dp] = 0ull;

    auto compute = [&](int il) {
        const ulonglong2* wb = (const ulonglong2*)(sh + ((il & 3) << 12) + j * 128);
        const float* xb = xsh + il * 8;

        // vectorized x: 2 broadcast LDS.128 per batch
        float xr[4][8];
#pragma unroll
        for (int bi = 0; bi < 4; bi++) {
            const float4* xb4 = (const float4*)(xb + (b0 + bi) * 256);
            float4 lo = xb4[0], hi = xb4[1];
            xr[bi][0] = lo.x; xr[bi][1] = lo.y; xr[bi][2] = lo.z; xr[bi][3] = lo.w;
            xr[bi][4] = hi.x; xr[bi][5] = hi.y; xr[bi][6] = hi.z; xr[bi][7] = hi.w;
        }

        u64 u2[4][DD / 2];
#pragma unroll
        for (int bi = 0; bi < 4; bi++)
#pragma unroll
            for (int dp = 0; dp < DD / 2; dp++) u2[bi][dp] = 0ull;

#pragma unroll
        for (int a = 0; a < DA; a++) {
            u64 xx[4];
#pragma unroll
            for (int bi = 0; bi < 4; bi++) xx[bi] = pack2(xr[bi][a], xr[bi][a]);
#pragma unroll
            for (int d4 = 0; d4 < 4; d4++) {
                ulonglong2 wv = wb[((a << 2) | d4) ^ j]; // conflict-free LDS.128
#pragma unroll
                for (int bi = 0; bi < 4; bi++) {
                    u2[bi][2 * d4]     = ffma2(wv.x, xx[bi], u2[bi][2 * d4]);
                    u2[bi][2 * d4 + 1] = ffma2(wv.y, xx[bi], u2[bi][2 * d4 + 1]);
                }
            }
        }

#pragma unroll
        for (int bi = 0; bi < 4; bi++) {
            const ulonglong2* vp =
                (const ulonglong2*)(vsh + ((b0 + bi) * JJ + j) * VSTRIDE);
            u64 lp = 0ull;
#pragma unroll
            for (int k = 0; k < 4; k++) {
                ulonglong2 vv = vp[k];
                lp = ffma2(u2[bi][2 * k],     vv.x, lp);
                lp = ffma2(u2[bi][2 * k + 1], vv.y, lp);
            }
            float lo, hi; unpack2(lp, lo, hi);
            // softmax over j = lanes (logits bounded -> skip max-subtract)
            float e = __expf(lo + hi);
            float z = e;
#pragma unroll
            for (int off = 16; off > 0; off >>= 1)
                z += __shfl_xor_sync(0xffffffffu, z, off);
            float c = __fdividef(e, z);
            u64 cc = pack2(c, c);
#pragma unroll
            for (int dp = 0; dp < DD / 2; dp++)
                acc2[bi][dp] = ffma2(cc, u2[bi][dp], acc2[bi][dp]);
        }
    };

    for (int pp = 0; pp < CHUNK / 2; ++pp) {
        const int il0 = 2 * pp;
        compute(il0);
        if (pp + 1 < CHUNK / 2) {
            stage_store(sh + (((il0 + 2) & 3) << 12), g, sj, sq0, ssub);
            stage_load(g, Wg4, sj, sf, i0 + il0 + 3);
        }
        compute(il0 + 1);
        if (pp + 1 < CHUNK / 2) {
            stage_store(sh + (((il0 + 3) & 3) << 12), g, sj, sq0, ssub);
            if (pp + 2 < CHUNK / 2)
                stage_load(g, Wg4, sj, sf, i0 + il0 + 4);
            __syncthreads();
        }
    }

#pragma unroll
    for (int bi = 0; bi < 4; bi++) {
        u64* p = (u64*)&g_partial[((blockIdx.x * BB + (b0 + bi)) * JJ + j) * DD];
#pragma unroll
        for (int dp = 0; dp < DD / 2; dp++) p[dp] = acc2[bi][dp];
    }
}

// ---------------------------------------------------------------------------
// Squash: 128 CTAs x 1024 threads, 8-way chunk split, 6-way MLP per thread.
// ---------------------------------------------------------------------------
template <int ROUND>
__global__ void __launch_bounds__(1024)
squash_kernel(float* __restrict__ out) {
    __shared__ float red[1024];
    const int tt = threadIdx.x & 127;
    const int o  = (int)blockIdx.x * 128 + tt;  // (b*JJ+j)*DD + d
    const int qq = threadIdx.x >> 7;            // chunk slice 0..7

    const float* p = g_partial + qq * 18 * OUTSZ + o;
    float s0 = 0.f, s1 = 0.f, s2 = 0.f, s3 = 0.f, s4 = 0.f, s5 = 0.f;
#pragma unroll
    for (int c = 0; c < 18; c += 6) {
        s0 += p[(c + 0) * OUTSZ];
        s1 += p[(c + 1) * OUTSZ];
        s2 += p[(c + 2) * OUTSZ];
        s3 += p[(c + 3) * OUTSZ];
        s4 += p[(c + 4) * OUTSZ];
        s5 += p[(c + 5) * OUTSZ];
    }
    red[threadIdx.x] = ((s0 + s1) + (s2 + s3)) + (s4 + s5);
    __syncthreads();

    if (qq == 0) {
        float s = ((red[tt] + red[tt + 128]) + (red[tt + 256] + red[tt + 384]))
                + ((red[tt + 512] + red[tt + 640]) + (red[tt + 768] + red[tt + 896]));
        if (ROUND == 0) s *= 0.03125f;  // uniform c = 1/32 folded here

        float sq = s * s;  // d-groups of 16 aligned within the warp
#pragma unroll
        for (int off = 8; off > 0; off >>= 1)
            sq += __shfl_xor_sync(0xffffffffu, sq, off);

        float v = s * (sq / ((1.0f + sq) * sqrtf(sq + CAP_EPS)));

        if (ROUND == 0)      g_vsum[o] = v;
        else if (ROUND == 1) g_vsum[o] += v;
        else                 out[o] = v;
    }
}

// ---------------------------------------------------------------------------
extern "C" void kernel_launch(void* const* d_in, const int* in_sizes, int n_in,
                              void* d_out, int out_size) {
    (void)in_sizes; (void)n_in; (void)out_size;
    const float* xg = (const float*)d_in[0];   // inputs [32,4608,8]
    const float* Wg = (const float*)d_in[1];   // W      [32,4608,16,8]
    float* out = (float*)d_out;                // [32,32,16]

    const int SMEM0 = 98304;        // pass0: ring 64KB + x 32KB
    const int SMEM  = 45056 * 4;    // pass1/2: 176 KB
    cudaFuncSetAttribute(pass0_kernel,   cudaFuncAttributeMaxDynamicSharedMemorySize, SMEM0);
    cudaFuncSetAttribute(pass_kernel<1>, cudaFuncAttributeMaxDynamicSharedMemorySize, SMEM);
    cudaFuncSetAttribute(pass_kernel<2>, cudaFuncAttributeMaxDynamicSharedMemorySize, SMEM);

    pass0_kernel<<<NCHUNK, 512, SMEM0>>>(xg, Wg);
    squash_kernel<0><<<128, 1024>>>(out);
    pass_kernel<1><<<NCHUNK, 256, SMEM>>>(xg, Wg);
    squash_kernel<1><<<128, 1024>>>(out);
    pass_kernel<2><<<NCHUNK, 256, SMEM>>>(xg, Wg);
    squash_kernel<2><<<128, 1024>>>(out);
}

// round 13
// speedup vs baseline: 1.0303x; 1.0303x over previous
#include <cuda_runtime.h>

// CapsuleLayer dynamic routing: 3 streaming passes (u_hat recomputed from W;
// b_ij == u_hat·(v0+..+v_{r-1})) + 3 squash kernels.
// R12 = R11 resubmitted unchanged (container infra flake; kernel audited clean
// twice). R9 passes 1/2 + squash (proven) with pass 0 re-tiled for 2 CTAs/SM:
// CHUNK0=16, 288 CTAs, 80KB smem/CTA, launch_bounds(256,2) -> cross-CTA
// latency/barrier hiding (pass0 has no v and no softmax, so smem is small).

#define BB 32
#define JJ 32
#define II 4608
#define DA 8
#define DD 16
#define CHUNK 32               // passes 1/2
#define NCHUNK 144
#define CHUNK0 16              // pass 0
#define NCHUNK0 288
#define OUTSZ (BB * JJ * DD)   // 16384
#define CAP_EPS 1e-7f
#define VSTRIDE 20             // padded v row: conflict-free LDS.128

typedef unsigned long long u64;

__device__ float g_partial[NCHUNK0 * OUTSZ]; // per-chunk partial s (18.9 MB)
__device__ float g_vsum[OUTSZ];              // v0, then v0+v1

__device__ __forceinline__ u64 pack2(float x, float y) {
    u64 r; asm("mov.b64 %0, {%1, %2};" : "=l"(r) : "f"(x), "f"(y)); return r;
}
__device__ __forceinline__ void unpack2(u64 v, float& x, float& y) {
    asm("mov.b64 {%0, %1}, %2;" : "=f"(x), "=f"(y) : "l"(v));
}
__device__ __forceinline__ u64 ffma2(u64 a, u64 b, u64 c) {
    u64 d; asm("fma.rn.f32x2 %0, %1, %2, %3;" : "=l"(d) : "l"(a), "l"(b), "l"(c)); return d;
}

// W tile staging: tile for i is [32 j][128 z] floats (z = d*8+a in global),
// stored transposed to [a][d] per j with float4-XOR swizzle:
// float z' = a*16+d at  phys = j*128 + ((z'>>2) ^ j)*4 + (z'&3).
__device__ __forceinline__ void stage_load(float4* g, const float4* Wg4,
                                           int sj, int sf, int ig) {
#pragma unroll
    for (int k = 0; k < 4; k++) g[k] = Wg4[(sj * II + ig) * 32 + k * 8 + sf];
}
__device__ __forceinline__ void stage_store(float* slot, const float4* g,
                                            int sj, int sq0, int ssub) {
    float* row = slot + sj * 128;
#pragma unroll
    for (int k = 0; k < 4; k++) {
        row[((sq0 + 0  + k) ^ sj) * 4 + ssub] = g[k].x;
        row[((sq0 + 4  + k) ^ sj) * 4 + ssub] = g[k].y;
        row[((sq0 + 8  + k) ^ sj) * 4 + ssub] = g[k].z;
        row[((sq0 + 12 + k) ^ sj) * 4 + ssub] = g[k].w;
    }
}

// ---------------------------------------------------------------------------
// PASS 0: uniform c (folded into squash). 288 CTAs (16-i chunk), 256 threads,
// 2 CTAs/SM. lane = j; warp w owns batches 4w..4w+3.
// Dynamic shared (81920 B): [0,16384) W ring 4 slots | [16384,20480) x chunk
//   xsh[b*128 + il*8 + a]
// ---------------------------------------------------------------------------
__global__ void __launch_bounds__(256, 2)
pass0_kernel(const float* __restrict__ xg, const float* __restrict__ Wg) {
    extern __shared__ float sh[];
    float* xsh = sh + 16384;
    const float4* Wg4 = (const float4*)Wg;

    const int t  = threadIdx.x;
    const int j  = t & 31;
    const int w  = t >> 5;
    const int b0 = w * 4;
    const int i0 = blockIdx.x * CHUNK0;
    const int sj   = t >> 3;
    const int sf   = t & 7;
    const int ssub = sf >> 1;
    const int sq0  = (sf & 1) << 4;

    // x: 16-i chunk, contiguous 128 floats per b
    for (int idx = t; idx < 4096; idx += 256) {
        int b = idx >> 7;
        xsh[idx] = xg[b * (II * DA) + i0 * DA + (idx & 127)];
    }

    float4 g[4];
    stage_load(g, Wg4, sj, sf, i0 + 0);
    stage_store(sh, g, sj, sq0, ssub);
    stage_load(g, Wg4, sj, sf, i0 + 1);
    stage_store(sh + 4096, g, sj, sq0, ssub);
    stage_load(g, Wg4, sj, sf, i0 + 2);
    __syncthreads();

    u64 acc2[4][DD / 2];
#pragma unroll
    for (int bi = 0; bi < 4; bi++)
#pragma unroll
        for (int dp = 0; dp < DD / 2; dp++) acc2[bi][dp] = 0ull;

    auto compute0 = [&](int il) {
        const ulonglong2* wb = (const ulonglong2*)(sh + ((il & 3) << 12) + j * 128);
        const float* xb = xsh + il * 8;
#pragma unroll
        for (int a = 0; a < DA; a++) {
            u64 xx[4];
#pragma unroll
            for (int bi = 0; bi < 4; bi++) {
                float xv = xb[(b0 + bi) * 128 + a];      // broadcast LDS
                xx[bi] = pack2(xv, xv);
            }
#pragma unroll
            for (int d4 = 0; d4 < 4; d4++) {
                ulonglong2 wv = wb[((a << 2) | d4) ^ j]; // conflict-free LDS.128
#pragma unroll
                for (int bi = 0; bi < 4; bi++) {
                    acc2[bi][2 * d4]     = ffma2(wv.x, xx[bi], acc2[bi][2 * d4]);
                    acc2[bi][2 * d4 + 1] = ffma2(wv.y, xx[bi], acc2[bi][2 * d4 + 1]);
                }
            }
        }
    };

    for (int pp = 0; pp < CHUNK0 / 2; ++pp) {
        const int il0 = 2 * pp;
        compute0(il0);
        if (pp + 1 < CHUNK0 / 2) {
            stage_store(sh + (((il0 + 2) & 3) << 12), g, sj, sq0, ssub);
            stage_load(g, Wg4, sj, sf, i0 + il0 + 3);
        }
        compute0(il0 + 1);
        if (pp + 1 < CHUNK0 / 2) {
            stage_store(sh + (((il0 + 3) & 3) << 12), g, sj, sq0, ssub);
            if (pp + 2 < CHUNK0 / 2)
                stage_load(g, Wg4, sj, sf, i0 + il0 + 4);
            __syncthreads();
        }
    }

#pragma unroll
    for (int bi = 0; bi < 4; bi++) {
        u64* p = (u64*)&g_partial[((blockIdx.x * BB + (b0 + bi)) * JJ + j) * DD];
#pragma unroll
        for (int dp = 0; dp < DD / 2; dp++) p[dp] = acc2[bi][dp];
    }
}

// ---------------------------------------------------------------------------
// PASS 1/2 (exact R9 structure): 256 threads, lane=j, warp owns 4 batches.
// Shared (180224 B): [0,16384) ring | [16384,24576) x | [24576,45056) v padded
// ---------------------------------------------------------------------------
template <int PASS>
__global__ void __launch_bounds__(256, 1)
pass_kernel(const float* __restrict__ xg, const float* __restrict__ Wg) {
    extern __shared__ float sh[];
    float* xsh = sh + 16384;
    float* vsh = sh + 24576;
    const float4* Wg4 = (const float4*)Wg;

    const int t  = threadIdx.x;
    const int j  = t & 31;
    const int w  = t >> 5;
    const int b0 = w * 4;
    const int i0 = blockIdx.x * CHUNK;
    const int sj   = t >> 3;
    const int sf   = t & 7;
    const int ssub = sf >> 1;
    const int sq0  = (sf & 1) << 4;

    // v -> padded shared
    for (int e = t; e < OUTSZ; e += 256) {
        int bj = e >> 4;
        vsh[bj * VSTRIDE + (e & 15)] = g_vsum[e];
    }
    // x: full chunk, contiguous 256 floats per b
    for (int idx = t; idx < 8192; idx += 256) {
        int b = idx >> 8;
        xsh[idx] = xg[b * (II * DA) + i0 * DA + (idx & 255)];
    }

    float4 g[4];
    stage_load(g, Wg4, sj, sf, i0 + 0);
    stage_store(sh, g, sj, sq0, ssub);
    stage_load(g, Wg4, sj, sf, i0 + 1);
    stage_store(sh + 4096, g, sj, sq0, ssub);
    stage_load(g, Wg4, sj, sf, i0 + 2);
    __syncthreads();

    u64 acc2[4][DD / 2];
#pragma unroll
    for (int bi = 0; bi < 4; bi++)
#pragma unroll
        for (int dp = 0; dp < DD / 2; dp++) acc2[bi][dp] = 0ull;

    auto compute = [&](int il) {
        const ulonglong2* wb = (const ulonglong2*)(sh + ((il & 3) << 12) + j * 128);
        const float* xb = xsh + il * 8;

        u64 u2[4][DD / 2];
#pragma unroll
        for (int bi = 0; bi < 4; bi++)
#pragma unroll
            for (int dp = 0; dp < DD / 2; dp++) u2[bi][dp] = 0ull;

#pragma unroll
        for (int a = 0; a < DA; a++) {
            u64 xx[4];
#pragma unroll
            for (int bi = 0; bi < 4; bi++) {
                float xv = xb[(b0 + bi) * 256 + a];      // broadcast LDS
                xx[bi] = pack2(xv, xv);
            }
#pragma unroll
            for (int d4 = 0; d4 < 4; d4++) {
                ulonglong2 wv = wb[((a << 2) | d4) ^ j]; // conflict-free LDS.128
#pragma unroll
                for (int bi = 0; bi < 4; bi++) {
                    u2[bi][2 * d4]     = ffma2(wv.x, xx[bi], u2[bi][2 * d4]);
                    u2[bi][2 * d4 + 1] = ffma2(wv.y, xx[bi], u2[bi][2 * d4 + 1]);
                }
            }
        }

#pragma unroll
        for (int bi = 0; bi < 4; bi++) {
            const ulonglong2* vp =
                (const ulonglong2*)(vsh + ((b0 + bi) * JJ + j) * VSTRIDE);
            u64 lp = 0ull;
#pragma unroll
            for (int k = 0; k < 4; k++) {
                ulonglong2 vv = vp[k];
                lp = ffma2(u2[bi][2 * k],     vv.x, lp);
                lp = ffma2(u2[bi][2 * k + 1], vv.y, lp);
            }
            float lo, hi; unpack2(lp, lo, hi);
            // softmax over j = lanes (logits bounded -> skip max-subtract)
            float e = __expf(lo + hi);
            float z = e;
#pragma unroll
            for (int off = 16; off > 0; off >>= 1)
                z += __shfl_xor_sync(0xffffffffu, z, off);
            float c = __fdividef(e, z);
            u64 cc = pack2(c, c);
#pragma unroll
            for (int dp = 0; dp < DD / 2; dp++)
                acc2[bi][dp] = ffma2(cc, u2[bi][dp], acc2[bi][dp]);
        }
    };

    for (int pp = 0; pp < CHUNK / 2; ++pp) {
        const int il0 = 2 * pp;
        compute(il0);
        if (pp + 1 < CHUNK / 2) {
            stage_store(sh + (((il0 + 2) & 3) << 12), g, sj, sq0, ssub);
            stage_load(g, Wg4, sj, sf, i0 + il0 + 3);
        }
        compute(il0 + 1);
        if (pp + 1 < CHUNK / 2) {
            stage_store(sh + (((il0 + 3) & 3) << 12), g, sj, sq0, ssub);
            if (pp + 2 < CHUNK / 2)
                stage_load(g, Wg4, sj, sf, i0 + il0 + 4);
            __syncthreads();
        }
    }

#pragma unroll
    for (int bi = 0; bi < 4; bi++) {
        u64* p = (u64*)&g_partial[((blockIdx.x * BB + (b0 + bi)) * JJ + j) * DD];
#pragma unroll
        for (int dp = 0; dp < DD / 2; dp++) p[dp] = acc2[bi][dp];
    }
}

// ---------------------------------------------------------------------------
// Squash: 128 CTAs x 1024 threads. NCH chunk partials (288 round 0, else 144)
// split 8 ways, 6-way MLP per thread, combined in shared; 16-lane shfl.
// ---------------------------------------------------------------------------
template <int ROUND, int NCH>
__global__ void __launch_bounds__(1024)
squash_kernel(float* __restrict__ out) {
    __shared__ float red[1024];
    const int tt = threadIdx.x & 127;
    const int o  = (int)blockIdx.x * 128 + tt;  // (b*JJ+j)*DD + d
    const int qq = threadIdx.x >> 7;            // chunk slice 0..7
    const int SL = NCH / 8;                     // 36 or 18 (divisible by 6)

    const float* p = g_partial + qq * SL * OUTSZ + o;
    float s0 = 0.f, s1 = 0.f, s2 = 0.f, s3 = 0.f, s4 = 0.f, s5 = 0.f;
#pragma unroll
    for (int c = 0; c < SL; c += 6) {
        s0 += p[(c + 0) * OUTSZ];
        s1 += p[(c + 1) * OUTSZ];
        s2 += p[(c + 2) * OUTSZ];
        s3 += p[(c + 3) * OUTSZ];
        s4 += p[(c + 4) * OUTSZ];
        s5 += p[(c + 5) * OUTSZ];
    }
    red[threadIdx.x] = ((s0 + s1) + (s2 + s3)) + (s4 + s5);
    __syncthreads();

    if (qq == 0) {
        float s = ((red[tt] + red[tt + 128]) + (red[tt + 256] + red[tt + 384]))
                + ((red[tt + 512] + red[tt + 640]) + (red[tt + 768] + red[tt + 896]));
        if (ROUND == 0) s *= 0.03125f;  // uniform c = 1/32 folded here

        float sq = s * s;  // d-groups of 16 aligned within the warp
#pragma unroll
        for (int off = 8; off > 0; off >>= 1)
            sq += __shfl_xor_sync(0xffffffffu, sq, off);

        float v = s * (sq / ((1.0f + sq) * sqrtf(sq + CAP_EPS)));

        if (ROUND == 0)      g_vsum[o] = v;
        else if (ROUND == 1) g_vsum[o] += v;
        else                 out[o] = v;
    }
}

// ---------------------------------------------------------------------------
extern "C" void kernel_launch(void* const* d_in, const int* in_sizes, int n_in,
                              void* d_out, int out_size) {
    (void)in_sizes; (void)n_in; (void)out_size;
    const float* xg = (const float*)d_in[0];   // inputs [32,4608,8]
    const float* Wg = (const float*)d_in[1];   // W      [32,4608,16,8]
    float* out = (float*)d_out;                // [32,32,16]

    const int SMEM0 = 81920;      // pass0: ring 64KB + x 16KB (fits 2 CTAs/SM)
    const int SMEM  = 45056 * 4;  // pass1/2: 176 KB
    cudaFuncSetAttribute(pass0_kernel,   cudaFuncAttributeMaxDynamicSharedMemorySize, SMEM0);
    cudaFuncSetAttribute(pass_kernel<1>, cudaFuncAttributeMaxDynamicSharedMemorySize, SMEM);
    cudaFuncSetAttribute(pass_kernel<2>, cudaFuncAttributeMaxDynamicSharedMemorySize, SMEM);

    pass0_kernel<<<NCHUNK0, 256, SMEM0>>>(xg, Wg);
    squash_kernel<0, NCHUNK0><<<128, 1024>>>(out);
    pass_kernel<1><<<NCHUNK, 256, SMEM>>>(xg, Wg);
    squash_kernel<1, NCHUNK><<<128, 1024>>>(out);
    pass_kernel<2><<<NCHUNK, 256, SMEM>>>(xg, Wg);
    squash_kernel<2, NCHUNK><<<128, 1024>>>(out);
}

// round 16
// speedup vs baseline: 1.2230x; 1.1870x over previous
#include <cuda_runtime.h>
#include <cstdint>

// CapsuleLayer dynamic routing: 3 streaming passes + 3 squash kernels.
// R15 = R14 with the cvt.rna.tf32.f32 destination fixed (.b32 reg, not .f32).
// Pass 0 (pure GEMM, uniform routing weights) on tensor cores via legacy
// mma.sync.m16n8k8 tf32 (sm_80+ PTX -> works on sm_100 base target).
// Passes 1/2 + squash byte-identical to the 179.6us best (R9).

#define BB 32
#define JJ 32
#define II 4608
#define DA 8
#define DD 16
#define CHUNK 32
#define NCHUNK 144
#define OUTSZ (BB * JJ * DD)   // 16384
#define CAP_EPS 1e-7f
#define VSTRIDE 20

typedef unsigned long long u64;

__device__ float g_partial[NCHUNK * OUTSZ]; // per-chunk partial s (9.4 MB)
__device__ float g_vsum[OUTSZ];             // v0, then v0+v1

__device__ __forceinline__ u64 pack2(float x, float y) {
    u64 r; asm("mov.b64 %0, {%1, %2};" : "=l"(r) : "f"(x), "f"(y)); return r;
}
__device__ __forceinline__ void unpack2(u64 v, float& x, float& y) {
    asm("mov.b64 {%0, %1}, %2;" : "=f"(x), "=f"(y) : "l"(v));
}
__device__ __forceinline__ u64 ffma2(u64 a, u64 b, u64 c) {
    u64 d; asm("fma.rn.f32x2 %0, %1, %2, %3;" : "=l"(d) : "l"(a), "l"(b), "l"(c)); return d;
}
// tf32 round: destination is a .b32 register (bit pattern of rounded float)
__device__ __forceinline__ float f2tf32(float x) {
    uint32_t r; asm("cvt.rna.tf32.f32 %0, %1;" : "=r"(r) : "f"(x));
    return __uint_as_float(r);
}
// D = A(16x8,row) @ B(8x8,col) + D, tf32 inputs, f32 accum.
__device__ __forceinline__ void mma_tf32(float c[4], const uint32_t a[4],
                                         const uint32_t b[2]) {
    asm volatile(
        "mma.sync.aligned.m16n8k8.row.col.f32.tf32.tf32.f32 "
        "{%0,%1,%2,%3}, {%4,%5,%6,%7}, {%8,%9}, {%0,%1,%2,%3};"
        : "+f"(c[0]), "+f"(c[1]), "+f"(c[2]), "+f"(c[3])
        : "r"(a[0]), "r"(a[1]), "r"(a[2]), "r"(a[3]), "r"(b[0]), "r"(b[1]));
}

// ---------------------------------------------------------------------------
// PASS 0 (tensor): 144 CTAs x 256 threads (8 warps). Per CTA: S0[b=32, jd=512]
// += X[b, (i,a)] W[jd, (i,a)] over K=256 (32 i x 8 a), via m16n8k8 tf32 mma.
// Warp w owns jd = w*64..w*64+63 (8 n-tiles) x 2 m-tiles; acc in regs.
// Smem (floats): [0,24576) B ring 4 slots x 6144 (B^T [jd][k], stride 12,
//   tf32-rounded) | [24576,32896) X chunk [b][260] tf32-rounded.
// Total 131584 B.
// ---------------------------------------------------------------------------
__device__ __forceinline__ void b_load(float4* g, const float4* Wg4,
                                       int t, int ig) {
#pragma unroll
    for (int k = 0; k < 4; k++) {
        int f4 = t + k * 256;
        int j = f4 >> 5, m = f4 & 31;            // m = d*2 + h
        g[k] = Wg4[(j * II + ig) * 32 + m];      // coalesced (j-block = 512B)
    }
}
__device__ __forceinline__ void b_store(float* slot, const float4* g, int t) {
#pragma unroll
    for (int k = 0; k < 4; k++) {
        int f4 = t + k * 256;
        int j = f4 >> 5, d = (f4 & 31) >> 1, h = f4 & 1;
        float* p = slot + (j * 16 + d) * 12 + 4 * h;   // row jd=j*16+d, k=4h..
        p[0] = f2tf32(g[k].x); p[1] = f2tf32(g[k].y);
        p[2] = f2tf32(g[k].z); p[3] = f2tf32(g[k].w);
    }
}

__global__ void __launch_bounds__(256, 1)
pass0_kernel(const float* __restrict__ xg, const float* __restrict__ Wg) {
    extern __shared__ float sh[];
    float* xsh = sh + 24576;
    const float4* Wg4 = (const float4*)Wg;

    const int t    = threadIdx.x;
    const int w    = t >> 5;
    const int lane = t & 31;
    const int g4   = lane >> 2;     // groupID
    const int tig  = lane & 3;      // thread-in-group
    const int i0   = blockIdx.x * CHUNK;

    // X chunk, tf32-rounded: xsh[b*260 + (il*8+a)]  (260: bank-conflict-free)
    for (int e = t; e < 8192; e += 256) {
        int b = e >> 8, r = e & 255;
        xsh[b * 260 + r] = f2tf32(xg[b * (II * DA) + i0 * DA + r]);
    }

    // B prologue: slots 0,1 staged; i0+2 prefetched into regs
    float4 g[4];
    b_load(g, Wg4, t, i0 + 0); b_store(sh,        g, t);
    b_load(g, Wg4, t, i0 + 1); b_store(sh + 6144, g, t);
    b_load(g, Wg4, t, i0 + 2);
    __syncthreads();

    float c[2][8][4];
#pragma unroll
    for (int mt = 0; mt < 2; mt++)
#pragma unroll
        for (int nt = 0; nt < 8; nt++)
#pragma unroll
            for (int e = 0; e < 4; e++) c[mt][nt][e] = 0.f;

    auto compute = [&](int il) {
        const float* wsl = sh + (il & 3) * 6144;
        const float* xb  = xsh + il * 8 + tig;
        uint32_t A[2][4];
#pragma unroll
        for (int mt = 0; mt < 2; mt++) {
            const float* ab = xb + (mt * 16 + g4) * 260;
            A[mt][0] = __float_as_uint(ab[0]);          // (g4,    tig)
            A[mt][1] = __float_as_uint(ab[8 * 260]);    // (g4+8,  tig)
            A[mt][2] = __float_as_uint(ab[4]);          // (g4,    tig+4)
            A[mt][3] = __float_as_uint(ab[8 * 260 + 4]);// (g4+8,  tig+4)
        }
#pragma unroll
        for (int nt = 0; nt < 8; nt++) {
            const float* bb = wsl + (w * 64 + nt * 8 + g4) * 12 + tig;
            uint32_t B2[2] = { __float_as_uint(bb[0]),   // (k=tig,   n=g4)
                               __float_as_uint(bb[4]) }; // (k=tig+4, n=g4)
            mma_tf32(c[0][nt], A[0], B2);
            mma_tf32(c[1][nt], A[1], B2);
        }
    };

    for (int pp = 0; pp < CHUNK / 2; ++pp) {
        const int il0 = 2 * pp;
        compute(il0);
        if (pp + 1 < CHUNK / 2) {
            // slot (il0+2)&3 last read at compute(il0-2), before prev barrier
            b_store(sh + ((il0 + 2) & 3) * 6144, g, t);
            b_load(g, Wg4, t, i0 + il0 + 3);
        }
        compute(il0 + 1);
        if (pp + 1 < CHUNK / 2) {
            b_store(sh + ((il0 + 3) & 3) * 6144, g, t);
            if (pp + 2 < CHUNK / 2)
                b_load(g, Wg4, t, i0 + il0 + 4);
            __syncthreads();
        }
    }

    // epilogue: D(row=b, col=jd) -> g_partial[(chunk*32+b)*512 + jd]
    float* gp = g_partial + blockIdx.x * (BB * 512);
#pragma unroll
    for (int mt = 0; mt < 2; mt++) {
#pragma unroll
        for (int nt = 0; nt < 8; nt++) {
            int row = mt * 16 + g4;
            int col = w * 64 + nt * 8 + 2 * tig;
            *(u64*)&gp[row * 512 + col]       = pack2(c[mt][nt][0], c[mt][nt][1]);
            *(u64*)&gp[(row + 8) * 512 + col] = pack2(c[mt][nt][2], c[mt][nt][3]);
        }
    }
}

// ======================= fp32 passes 1/2 (exact R9) ========================
__device__ __forceinline__ void stage_load(float4* g, const float4* Wg4,
                                           int sj, int sf, int ig) {
#pragma unroll
    for (int k = 0; k < 4; k++) g[k] = Wg4[(sj * II + ig) * 32 + k * 8 + sf];
}
__device__ __forceinline__ void stage_store(float* slot, const float4* g,
                                            int sj, int sq0, int ssub) {
    float* row = slot + sj * 128;
#pragma unroll
    for (int k = 0; k < 4; k++) {
        row[((sq0 + 0  + k) ^ sj) * 4 + ssub] = g[k].x;
        row[((sq0 + 4  + k) ^ sj) * 4 + ssub] = g[k].y;
        row[((sq0 + 8  + k) ^ sj) * 4 + ssub] = g[k].z;
        row[((sq0 + 12 + k) ^ sj) * 4 + ssub] = g[k].w;
    }
}

template <int PASS>
__global__ void __launch_bounds__(256, 1)
pass_kernel(const float* __restrict__ xg, const float* __restrict__ Wg) {
    extern __shared__ float sh[];
    float* xsh = sh + 16384;
    float* vsh = sh + 24576;
    const float4* Wg4 = (const float4*)Wg;

    const int t  = threadIdx.x;
    const int j  = t & 31;
    const int w  = t >> 5;
    const int b0 = w * 4;
    const int i0 = blockIdx.x * CHUNK;
    const int sj   = t >> 3;
    const int sf   = t & 7;
    const int ssub = sf >> 1;
    const int sq0  = (sf & 1) << 4;

    for (int e = t; e < OUTSZ; e += 256) {
        int bj = e >> 4;
        vsh[bj * VSTRIDE + (e & 15)] = g_vsum[e];
    }
    for (int idx = t; idx < 8192; idx += 256) {
        int b = idx >> 8;
        xsh[idx] = xg[b * (II * DA) + i0 * DA + (idx & 255)];
    }

    float4 g[4];
    stage_load(g, Wg4, sj, sf, i0 + 0);
    stage_store(sh, g, sj, sq0, ssub);
    stage_load(g, Wg4, sj, sf, i0 + 1);
    stage_store(sh + 4096, g, sj, sq0, ssub);
    stage_load(g, Wg4, sj, sf, i0 + 2);
    __syncthreads();

    u64 acc2[4][DD / 2];
#pragma unroll
    for (int bi = 0; bi < 4; bi++)
#pragma unroll
        for (int dp = 0; dp < DD / 2; dp++) acc2[bi][dp] = 0ull;

    auto compute = [&](int il) {
        const ulonglong2* wb = (const ulonglong2*)(sh + ((il & 3) << 12) + j * 128);
        const float* xb = xsh + il * 8;

        u64 u2[4][DD / 2];
#pragma unroll
        for (int bi = 0; bi < 4; bi++)
#pragma unroll
            for (int dp = 0; dp < DD / 2; dp++) u2[bi][dp] = 0ull;

#pragma unroll
        for (int a = 0; a < DA; a++) {
            u64 xx[4];
#pragma unroll
            for (int bi = 0; bi < 4; bi++) {
                float xv = xb[(b0 + bi) * 256 + a];      // broadcast LDS
                xx[bi] = pack2(xv, xv);
            }
#pragma unroll
            for (int d4 = 0; d4 < 4; d4++) {
                ulonglong2 wv = wb[((a << 2) | d4) ^ j]; // conflict-free LDS.128
#pragma unroll
                for (int bi = 0; bi < 4; bi++) {
                    u2[bi][2 * d4]     = ffma2(wv.x, xx[bi], u2[bi][2 * d4]);
                    u2[bi][2 * d4 + 1] = ffma2(wv.y, xx[bi], u2[bi][2 * d4 + 1]);
                }
            }
        }

#pragma unroll
        for (int bi = 0; bi < 4; bi++) {
            const ulonglong2* vp =
                (const ulonglong2*)(vsh + ((b0 + bi) * JJ + j) * VSTRIDE);
            u64 lp = 0ull;
#pragma unroll
            for (int k = 0; k < 4; k++) {
                ulonglong2 vv = vp[k];
                lp = ffma2(u2[bi][2 * k],     vv.x, lp);
                lp = ffma2(u2[bi][2 * k + 1], vv.y, lp);
            }
            float lo, hi; unpack2(lp, lo, hi);
            // softmax over j = lanes (logits bounded -> skip max-subtract)
            float e = __expf(lo + hi);
            float z = e;
#pragma unroll
            for (int off = 16; off > 0; off >>= 1)
                z += __shfl_xor_sync(0xffffffffu, z, off);
            float c = __fdividef(e, z);
            u64 cc = pack2(c, c);
#pragma unroll
            for (int dp = 0; dp < DD / 2; dp++)
                acc2[bi][dp] = ffma2(cc, u2[bi][dp], acc2[bi][dp]);
        }
    };

    for (int pp = 0; pp < CHUNK / 2; ++pp) {
        const int il0 = 2 * pp;
        compute(il0);
        if (pp + 1 < CHUNK / 2) {
            stage_store(sh + (((il0 + 2) & 3) << 12), g, sj, sq0, ssub);
            stage_load(g, Wg4, sj, sf, i0 + il0 + 3);
        }
        compute(il0 + 1);
        if (pp + 1 < CHUNK / 2) {
            stage_store(sh + (((il0 + 3) & 3) << 12), g, sj, sq0, ssub);
            if (pp + 2 < CHUNK / 2)
                stage_load(g, Wg4, sj, sf, i0 + il0 + 4);
            __syncthreads();
        }
    }

#pragma unroll
    for (int bi = 0; bi < 4; bi++) {
        u64* p = (u64*)&g_partial[((blockIdx.x * BB + (b0 + bi)) * JJ + j) * DD];
#pragma unroll
        for (int dp = 0; dp < DD / 2; dp++) p[dp] = acc2[bi][dp];
    }
}

// ======================= squash (exact R9) =================================
template <int ROUND>
__global__ void __launch_bounds__(1024)
squash_kernel(float* __restrict__ out) {
    __shared__ float red[1024];
    const int tt = threadIdx.x & 127;
    const int o  = (int)blockIdx.x * 128 + tt;  // (b*JJ+j)*DD + d
    const int qq = threadIdx.x >> 7;            // chunk slice 0..7

    const float* p = g_partial + qq * 18 * OUTSZ + o;
    float s0 = 0.f, s1 = 0.f, s2 = 0.f;
#pragma unroll
    for (int c = 0; c < 18; c += 3) {
        s0 += p[(c + 0) * OUTSZ];
        s1 += p[(c + 1) * OUTSZ];
        s2 += p[(c + 2) * OUTSZ];
    }
    red[threadIdx.x] = (s0 + s1) + s2;
    __syncthreads();

    if (qq == 0) {
        float s = ((red[tt] + red[tt + 128]) + (red[tt + 256] + red[tt + 384]))
                + ((red[tt + 512] + red[tt + 640]) + (red[tt + 768] + red[tt + 896]));
        if (ROUND == 0) s *= 0.03125f;  // uniform c = 1/32 folded here

        float sq = s * s;  // d-groups of 16 aligned within the warp
#pragma unroll
        for (int off = 8; off > 0; off >>= 1)
            sq += __shfl_xor_sync(0xffffffffu, sq, off);

        float v = s * (sq / ((1.0f + sq) * sqrtf(sq + CAP_EPS)));

        if (ROUND == 0)      g_vsum[o] = v;
        else if (ROUND == 1) g_vsum[o] += v;
        else                 out[o] = v;
    }
}

// ---------------------------------------------------------------------------
extern "C" void kernel_launch(void* const* d_in, const int* in_sizes, int n_in,
                              void* d_out, int out_size) {
    (void)in_sizes; (void)n_in; (void)out_size;
    const float* xg = (const float*)d_in[0];   // inputs [32,4608,8]
    const float* Wg = (const float*)d_in[1];   // W      [32,4608,16,8]
    float* out = (float*)d_out;                // [32,32,16]

    const int SMEM0 = 131584;     // pass0: B ring 96KB + X 32.5KB
    const int SMEM  = 45056 * 4;  // pass1/2: 176 KB
    cudaFuncSetAttribute(pass0_kernel,   cudaFuncAttributeMaxDynamicSharedMemorySize, SMEM0);
    cudaFuncSetAttribute(pass_kernel<1>, cudaFuncAttributeMaxDynamicSharedMemorySize, SMEM);
    cudaFuncSetAttribute(pass_kernel<2>, cudaFuncAttributeMaxDynamicSharedMemorySize, SMEM);

    pass0_kernel<<<NCHUNK, 256, SMEM0>>>(xg, Wg);
    squash_kernel<0><<<128, 1024>>>(out);
    pass_kernel<1><<<NCHUNK, 256, SMEM>>>(xg, Wg);
    squash_kernel<1><<<128, 1024>>>(out);
    pass_kernel<2><<<NCHUNK, 256, SMEM>>>(xg, Wg);
    squash_kernel<2><<<128, 1024>>>(out);
}